// round 13
// baseline (speedup 1.0000x reference)
#include <cuda_runtime.h>
#include <cuda_bf16.h>
#include <cstdint>

#define K_BANDS 36
#define EMBED   128
#define MAXF    130
#define KPMAX   144
#define NB_TOT  1025
#define T_LEN   2048
#define B_SZ    8
#define TT      64
#define EPS     1e-5f

// ---- device scratch ----
__device__ float g_S1[K_BANDS * EMBED];
__device__ float g_S2[K_BANDS * EMBED];
// Wg hi/lo bf16x2 pairs, [k][e][KPMAX/2] (k-contig per e), zero-padded
__device__ __align__(16) unsigned g_Bh[K_BANDS * EMBED * (KPMAX / 2)];
__device__ __align__(16) unsigned g_Bl[K_BANDS * EMBED * (KPMAX / 2)];

__device__ __forceinline__ void band_params(int k, int& nb, int& start) {
    if (k < 20)      { nb = 16; start = 16 * k; }
    else if (k < 30) { nb = 32; start = 320 + 32 * (k - 20); }
    else if (k < 35) { nb = 64; start = 640 + 64 * (k - 30); }
    else             { nb = 65; start = 960; }
}

// grid (36, 8), 128 threads.
__global__ void prep_kernel(const float* __restrict__ W,
                            const float* __restrict__ gamma,
                            const float* __restrict__ beta,
                            const float* __restrict__ bias) {
    const int k = blockIdx.x, q = blockIdx.y;
    const int tid = threadIdx.x;
    int nb, start; band_params(k, nb, start);
    const int f = 2 * nb;
    const float* gk = gamma + (size_t)k * MAXF;
    const float* bk = beta  + (size_t)k * MAXF;

    {
        int el = tid >> 3, l = tid & 7;
        int e = q * 16 + el;
        const float* Wk = W + ((size_t)k * EMBED + e) * MAXF;
        float s1 = 0.f, s2 = 0.f;
        for (int ff = l; ff < f; ff += 8) {
            float w = Wk[ff];
            s1 += w * gk[ff];
            s2 += w * bk[ff];
        }
#pragma unroll
        for (int d = 1; d < 8; d <<= 1) {
            s1 += __shfl_xor_sync(0xFFFFFFFFu, s1, d);
            s2 += __shfl_xor_sync(0xFFFFFFFFu, s2, d);
        }
        if (l == 0) {
            g_S1[k * EMBED + e] = s1;
            g_S2[k * EMBED + e] = s2 + bias[k * EMBED + e];
        }
    }

    for (int idx = q * 1152 + tid; idx < (q + 1) * 1152; idx += 128) {
        int e = idx / (KPMAX / 2);
        int p = idx % (KPMAX / 2);
        int k0 = 2 * p, k1 = 2 * p + 1;
        const float* Wk = W + ((size_t)k * EMBED + e) * MAXF;
        float w0 = (k0 < f) ? Wk[k0] * gk[k0] : 0.f;
        float w1 = (k1 < f) ? Wk[k1] * gk[k1] : 0.f;
        __nv_bfloat162 h = __floats2bfloat162_rn(w0, w1);
        float2 hf = __bfloat1622float2(h);
        __nv_bfloat162 l = __floats2bfloat162_rn(w0 - hf.x, w1 - hf.y);
        size_t o = (size_t)k * EMBED * (KPMAX / 2) + idx;
        g_Bh[o] = *(unsigned*)&h;
        g_Bl[o] = *(unsigned*)&l;
    }
}

// ---- ptx helpers ----
__device__ __forceinline__ uint32_t smem_u32(const void* p) {
    uint32_t a;
    asm("{ .reg .u64 t; cvta.to.shared.u64 t, %1; cvt.u32.u64 %0, t; }" : "=r"(a) : "l"(p));
    return a;
}
__device__ __forceinline__ void cp16(uint32_t dst, const void* src) {
    asm volatile("cp.async.ca.shared.global [%0], [%1], 16;" :: "r"(dst), "l"(src));
}
#define CP_COMMIT() asm volatile("cp.async.commit_group;")
#define CP_WAIT0()  asm volatile("cp.async.wait_group 0;")

__device__ __forceinline__ void ldsm_x4(uint32_t* r, uint32_t addr) {
    asm volatile("ldmatrix.sync.aligned.m8n8.x4.shared.b16 {%0,%1,%2,%3}, [%4];"
        : "=r"(r[0]), "=r"(r[1]), "=r"(r[2]), "=r"(r[3]) : "r"(addr));
}
__device__ __forceinline__ void mma_bf16(float* c, const uint32_t* a, const uint32_t* b) {
    asm volatile("mma.sync.aligned.m16n8k16.row.col.f32.bf16.bf16.f32 "
        "{%0,%1,%2,%3}, {%4,%5,%6,%7}, {%8,%9}, {%0,%1,%2,%3};"
        : "+f"(c[0]), "+f"(c[1]), "+f"(c[2]), "+f"(c[3])
        : "r"(a[0]), "r"(a[1]), "r"(a[2]), "r"(a[3]), "r"(b[0]), "r"(b[1]));
}
__device__ __forceinline__ unsigned cvt_bf2(float x, float y) {
    __nv_bfloat162 h = __floats2bfloat162_rn(x, y);
    return *(unsigned*)&h;
}

// ---- smem: B double-buffer (24.5KB), overlaid by epilogue out buffer [128][68]f32 ----
#define SB_B    0
#define SM_TOT  34816

__global__ __launch_bounds__(256, 3)
void band_main(const float* __restrict__ spec, float* __restrict__ out) {
    const int kb = 35 - blockIdx.z;          // heavy bands first
    const int b  = blockIdx.y;
    const int t0 = blockIdx.x * TT;
    int nb, start; band_params(kb, nb, start);
    const int f    = 2 * nb;
    const int kpad = (f + 15) & ~15;
    const int nch  = kpad >> 4;

    extern __shared__ __align__(16) char smem[];
    const uint32_t sb = smem_u32(smem);
    const int tid = threadIdx.x;
    const int wid = tid >> 5;
    const int lid = tid & 31;

    const unsigned* srcH = g_Bh + (size_t)kb * EMBED * (KPMAX / 2);
    const unsigned* srcL = g_Bl + (size_t)kb * EMBED * (KPMAX / 2);

    // ---- issue B chunk 0 ----
    for (int m = tid; m < 512; m += 256) {
        int typ = m & 1, half = (m >> 1) & 1, e = m >> 2;
        const unsigned* src = (typ ? srcL : srcH) + e * (KPMAX / 2) + half * 4;
        cp16(sb + SB_B + typ * 6144 + (e * 24 + half * 8) * 2, src);
    }
    CP_COMMIT();

    const int wm = wid & 1, wn = wid >> 1;
    const int tb = wm * 32, n0 = wn * 32;
    const int r  = lid >> 2, jl = lid & 3;
    const int lrow  = (lid & 7) + ((lid >> 4) << 3);
    const int lcol8 = ((lid >> 3) & 1) << 3;

    const float* spb = spec + (((size_t)b * NB_TOT + start) * T_LEN + t0) * 2;

    float acc[2][4][4];
#pragma unroll
    for (int m = 0; m < 2; ++m)
#pragma unroll
        for (int g = 0; g < 4; ++g)
#pragma unroll
            for (int q = 0; q < 4; ++q) acc[m][g][q] = 0.f;

    float st[2][2]  = {{0.f, 0.f}, {0.f, 0.f}};
    float st2[2][2] = {{0.f, 0.f}, {0.f, 0.f}};

    const float2 z2 = make_float2(0.f, 0.f);

    for (int c = 0; c < nch; ++c) {
        CP_WAIT0();
        __syncthreads();
        if (c + 1 < nch) {
            int buf = (c + 1) & 1;
            for (int m = tid; m < 512; m += 256) {
                int typ = m & 1, half = (m >> 1) & 1, e = m >> 2;
                const unsigned* src = (typ ? srcL : srcH) + e * (KPMAX / 2) + (c + 1) * 8 + half * 4;
                cp16(sb + SB_B + buf * 12288 + typ * 6144 + (e * 24 + half * 8) * 2, src);
            }
        }
        CP_COMMIT();

        // ---- build A fragments directly from gmem (no smem) ----
        const int j0 = 8 * c + jl, j1 = j0 + 4;
        const bool gd0 = j0 < nb, gd1 = j1 < nb;
        uint32_t ah[2][4], al[2][4];
#pragma unroll
        for (int mt = 0; mt < 2; ++mt) {
            const int ta = tb + mt * 16 + r;
            float2 v00 = gd0 ? *(const float2*)(spb + ((size_t)j0 * T_LEN + ta) * 2)     : z2;
            float2 v01 = gd0 ? *(const float2*)(spb + ((size_t)j0 * T_LEN + ta + 8) * 2) : z2;
            float2 v10 = gd1 ? *(const float2*)(spb + ((size_t)j1 * T_LEN + ta) * 2)     : z2;
            float2 v11 = gd1 ? *(const float2*)(spb + ((size_t)j1 * T_LEN + ta + 8) * 2) : z2;

            // stats: [mt][0] -> row ta, [mt][1] -> row ta+8
            st[mt][0]  += v00.x + v00.y + v10.x + v10.y;
            st2[mt][0] = fmaf(v00.x, v00.x, st2[mt][0]);
            st2[mt][0] = fmaf(v00.y, v00.y, st2[mt][0]);
            st2[mt][0] = fmaf(v10.x, v10.x, st2[mt][0]);
            st2[mt][0] = fmaf(v10.y, v10.y, st2[mt][0]);
            st[mt][1]  += v01.x + v01.y + v11.x + v11.y;
            st2[mt][1] = fmaf(v01.x, v01.x, st2[mt][1]);
            st2[mt][1] = fmaf(v01.y, v01.y, st2[mt][1]);
            st2[mt][1] = fmaf(v11.x, v11.x, st2[mt][1]);
            st2[mt][1] = fmaf(v11.y, v11.y, st2[mt][1]);

            // hi frags: a0=(row, klo) a1=(row+8, klo) a2=(row, khi) a3=(row+8, khi)
            ah[mt][0] = cvt_bf2(v00.x, v00.y);
            ah[mt][1] = cvt_bf2(v01.x, v01.y);
            ah[mt][2] = cvt_bf2(v10.x, v10.y);
            ah[mt][3] = cvt_bf2(v11.x, v11.y);
            // lo frags = residual
            float2 h0 = __bfloat1622float2(*(__nv_bfloat162*)&ah[mt][0]);
            float2 h1 = __bfloat1622float2(*(__nv_bfloat162*)&ah[mt][1]);
            float2 h2 = __bfloat1622float2(*(__nv_bfloat162*)&ah[mt][2]);
            float2 h3 = __bfloat1622float2(*(__nv_bfloat162*)&ah[mt][3]);
            al[mt][0] = cvt_bf2(v00.x - h0.x, v00.y - h0.y);
            al[mt][1] = cvt_bf2(v01.x - h1.x, v01.y - h1.y);
            al[mt][2] = cvt_bf2(v10.x - h2.x, v10.y - h2.y);
            al[mt][3] = cvt_bf2(v11.x - h3.x, v11.y - h3.y);
        }

        const uint32_t bbase = sb + SB_B + (c & 1) * 12288;
#pragma unroll
        for (int gg = 0; gg < 2; ++gg) {
            uint32_t bd = bbase + ((n0 + gg * 16 + lrow) * 24 + lcol8) * 2;
            uint32_t bh[4], bl[4];
            ldsm_x4(bh, bd);
            ldsm_x4(bl, bd + 6144);
#pragma unroll
            for (int m = 0; m < 2; ++m) {
                mma_bf16(acc[m][2 * gg],     ah[m], bh);
                mma_bf16(acc[m][2 * gg + 1], ah[m], bh + 2);
                mma_bf16(acc[m][2 * gg],     al[m], bh);
                mma_bf16(acc[m][2 * gg + 1], al[m], bh + 2);
                mma_bf16(acc[m][2 * gg],     ah[m], bl);
                mma_bf16(acc[m][2 * gg + 1], ah[m], bl + 2);
            }
        }
    }

    // ---- finalize stats in-register (lanes l^1,l^2 share same t rows) ----
    float mu[2][2], rs[2][2];
    {
        const float inv_f = 1.0f / (float)f;
#pragma unroll
        for (int mt = 0; mt < 2; ++mt)
#pragma unroll
            for (int h = 0; h < 2; ++h) {
                float s  = st[mt][h],  s2 = st2[mt][h];
                s  += __shfl_xor_sync(0xFFFFFFFFu, s, 1);
                s2 += __shfl_xor_sync(0xFFFFFFFFu, s2, 1);
                s  += __shfl_xor_sync(0xFFFFFFFFu, s, 2);
                s2 += __shfl_xor_sync(0xFFFFFFFFu, s2, 2);
                float m = s * inv_f;
                float var = fmaxf(s2 * inv_f - m * m, 0.f);
                mu[mt][h] = m;
                rs[mt][h] = rsqrtf(var + EPS);
            }
    }

    __syncthreads();   // all B smem reads done; overlay as out buffer [e][68]

    // ---- epilogue: y = rs*(acc - mu*S1) + S2 -> smem [e][68] ----
    {
        float* ob = (float*)smem;
#pragma unroll
        for (int mt = 0; mt < 2; ++mt) {
            int t1 = tb + mt * 16 + r;
#pragma unroll
            for (int g = 0; g < 4; ++g) {
                int e0 = n0 + g * 8 + (jl << 1);
                float2 s1 = *(const float2*)&g_S1[kb * EMBED + e0];
                float2 s2 = *(const float2*)&g_S2[kb * EMBED + e0];
                float* a4 = acc[mt][g];
                ob[e0 * 68 + t1]           = fmaf(rs[mt][0], fmaf(-mu[mt][0], s1.x, a4[0]), s2.x);
                ob[(e0 + 1) * 68 + t1]     = fmaf(rs[mt][0], fmaf(-mu[mt][0], s1.y, a4[1]), s2.y);
                ob[e0 * 68 + t1 + 8]       = fmaf(rs[mt][1], fmaf(-mu[mt][1], s1.x, a4[2]), s2.x);
                ob[(e0 + 1) * 68 + t1 + 8] = fmaf(rs[mt][1], fmaf(-mu[mt][1], s1.y, a4[3]), s2.y);
            }
        }
    }
    __syncthreads();

    // ---- store: warp covers 2 e-rows per iter, 256B contiguous each ----
    {
        const float* ob = (const float*)smem;
        const int er = lid >> 4, t4 = (lid & 15) * 4;
#pragma unroll
        for (int it = 0; it < 8; ++it) {
            int e = wid * 16 + it * 2 + er;
            float4 v = *(const float4*)&ob[e * 68 + t4];
            *(float4*)(out + (((size_t)b * EMBED + e) * K_BANDS + kb) * T_LEN + t0 + t4) = v;
        }
    }
}

extern "C" void kernel_launch(void* const* d_in, const int* in_sizes, int n_in,
                              void* d_out, int out_size) {
    const float* spec  = (const float*)d_in[0];
    const float* gamma = (const float*)d_in[1];
    const float* beta  = (const float*)d_in[2];
    const float* W     = (const float*)d_in[3];
    const float* bias  = (const float*)d_in[4];
    float* out = (float*)d_out;

    prep_kernel<<<dim3(K_BANDS, 8), 128>>>(W, gamma, beta, bias);

    cudaFuncSetAttribute(band_main, cudaFuncAttributeMaxDynamicSharedMemorySize, SM_TOT);
    dim3 grid(T_LEN / TT, B_SZ, K_BANDS);
    band_main<<<grid, 256, SM_TOT>>>(spec, out);
}

// round 14
// speedup vs baseline: 1.1695x; 1.1695x over previous
#include <cuda_runtime.h>
#include <cuda_bf16.h>
#include <cstdint>

#define K_BANDS 36
#define EMBED   128
#define MAXF    130
#define KPMAX   144
#define NB_TOT  1025
#define T_LEN   2048
#define B_SZ    8
#define TT      64
#define EPS     1e-5f

// ---- device scratch ----
__device__ float g_S1[K_BANDS * EMBED];
__device__ float g_S2[K_BANDS * EMBED];
// Wg hi/lo bf16x2 pairs, [k][e][KPMAX/2] (k-contig per e), zero-padded
__device__ __align__(16) unsigned g_Bh[K_BANDS * EMBED * (KPMAX / 2)];
__device__ __align__(16) unsigned g_Bl[K_BANDS * EMBED * (KPMAX / 2)];

__device__ __forceinline__ void band_params(int k, int& nb, int& start) {
    if (k < 20)      { nb = 16; start = 16 * k; }
    else if (k < 30) { nb = 32; start = 320 + 32 * (k - 20); }
    else if (k < 35) { nb = 64; start = 640 + 64 * (k - 30); }
    else             { nb = 65; start = 960; }
}

// grid (36, 8), 128 threads.
__global__ void prep_kernel(const float* __restrict__ W,
                            const float* __restrict__ gamma,
                            const float* __restrict__ beta,
                            const float* __restrict__ bias) {
    const int k = blockIdx.x, q = blockIdx.y;
    const int tid = threadIdx.x;
    int nb, start; band_params(k, nb, start);
    const int f = 2 * nb;
    const float* gk = gamma + (size_t)k * MAXF;
    const float* bk = beta  + (size_t)k * MAXF;

    {
        int el = tid >> 3, l = tid & 7;
        int e = q * 16 + el;
        const float* Wk = W + ((size_t)k * EMBED + e) * MAXF;
        float s1 = 0.f, s2 = 0.f;
        for (int ff = l; ff < f; ff += 8) {
            float w = Wk[ff];
            s1 += w * gk[ff];
            s2 += w * bk[ff];
        }
#pragma unroll
        for (int d = 1; d < 8; d <<= 1) {
            s1 += __shfl_xor_sync(0xFFFFFFFFu, s1, d);
            s2 += __shfl_xor_sync(0xFFFFFFFFu, s2, d);
        }
        if (l == 0) {
            g_S1[k * EMBED + e] = s1;
            g_S2[k * EMBED + e] = s2 + bias[k * EMBED + e];
        }
    }

    for (int idx = q * 1152 + tid; idx < (q + 1) * 1152; idx += 128) {
        int e = idx / (KPMAX / 2);
        int p = idx % (KPMAX / 2);
        int k0 = 2 * p, k1 = 2 * p + 1;
        const float* Wk = W + ((size_t)k * EMBED + e) * MAXF;
        float w0 = (k0 < f) ? Wk[k0] * gk[k0] : 0.f;
        float w1 = (k1 < f) ? Wk[k1] * gk[k1] : 0.f;
        __nv_bfloat162 h = __floats2bfloat162_rn(w0, w1);
        float2 hf = __bfloat1622float2(h);
        __nv_bfloat162 l = __floats2bfloat162_rn(w0 - hf.x, w1 - hf.y);
        size_t o = (size_t)k * EMBED * (KPMAX / 2) + idx;
        g_Bh[o] = *(unsigned*)&h;
        g_Bl[o] = *(unsigned*)&l;
    }
}

// ---- ptx helpers ----
__device__ __forceinline__ uint32_t smem_u32(const void* p) {
    uint32_t a;
    asm("{ .reg .u64 t; cvta.to.shared.u64 t, %1; cvt.u32.u64 %0, t; }" : "=r"(a) : "l"(p));
    return a;
}
__device__ __forceinline__ void cp16(uint32_t dst, const void* src) {
    asm volatile("cp.async.ca.shared.global [%0], [%1], 16;" :: "r"(dst), "l"(src));
}
#define CP_COMMIT() asm volatile("cp.async.commit_group;")
#define CP_WAIT0()  asm volatile("cp.async.wait_group 0;")

__device__ __forceinline__ void ldsm_x4(uint32_t* r, uint32_t addr) {
    asm volatile("ldmatrix.sync.aligned.m8n8.x4.shared.b16 {%0,%1,%2,%3}, [%4];"
        : "=r"(r[0]), "=r"(r[1]), "=r"(r[2]), "=r"(r[3]) : "r"(addr));
}
__device__ __forceinline__ void ldsm_x4_t(uint32_t* r, uint32_t addr) {
    asm volatile("ldmatrix.sync.aligned.m8n8.x4.trans.shared.b16 {%0,%1,%2,%3}, [%4];"
        : "=r"(r[0]), "=r"(r[1]), "=r"(r[2]), "=r"(r[3]) : "r"(addr));
}
__device__ __forceinline__ void mma_bf16(float* c, const uint32_t* a, const uint32_t* b) {
    asm volatile("mma.sync.aligned.m16n8k16.row.col.f32.bf16.bf16.f32 "
        "{%0,%1,%2,%3}, {%4,%5,%6,%7}, {%8,%9}, {%0,%1,%2,%3};"
        : "+f"(c[0]), "+f"(c[1]), "+f"(c[2]), "+f"(c[3])
        : "r"(a[0]), "r"(a[1]), "r"(a[2]), "r"(a[3]), "r"(b[0]), "r"(b[1]));
}

// ---- smem byte offsets ----
// A: [k<=144][t stride 72] bf16 hi/lo
#define SB_A_HI 0
#define SB_A_LO 20736
#define SB_B    41472          // 2 bufs x (hi 6144 + lo 6144); [e][k stride 24]
#define SB_PS   66048          // 8 x 64 floats
#define SB_PS2  68096
#define SB_MU   70144
#define SB_RS   70400
#define SB_S1   70656
#define SB_S2   71168
#define SM_TOT  71680

__global__ __launch_bounds__(256, 3)
void band_main(const float* __restrict__ spec, float* __restrict__ out) {
    const int kb = 35 - blockIdx.z;          // heavy bands first
    const int b  = blockIdx.y;
    const int t0 = blockIdx.x * TT;
    int nb, start; band_params(kb, nb, start);
    const int f    = 2 * nb;
    const int kpad = (f + 15) & ~15;
    const int nch  = kpad >> 4;

    extern __shared__ __align__(16) char smem[];
    const uint32_t sb = smem_u32(smem);
    const int tid = threadIdx.x;
    const int wid = tid >> 5;
    const int lid = tid & 31;

    const unsigned* srcH = g_Bh + (size_t)kb * EMBED * (KPMAX / 2);
    const unsigned* srcL = g_Bl + (size_t)kb * EMBED * (KPMAX / 2);

    // ---- issue B chunk 0 ----
    {
        for (int m = tid; m < 512; m += 256) {
            int typ = m & 1, half = (m >> 1) & 1, e = m >> 2;
            const unsigned* src = (typ ? srcL : srcH) + e * (KPMAX / 2) + half * 4;
            cp16(sb + SB_B + typ * 6144 + (e * 24 + half * 8) * 2, src);
        }
        CP_COMMIT();
    }

    // ---- fused stage A + stats: thread owns t-pair, 8-way k split ----
    {
        const int h  = tid >> 5;             // k-group 0..7
        const int t2 = lid * 2;              // t pair base 0..62
        const float* sp4 = spec + (((size_t)b * NB_TOT + start) * T_LEN + t0 + t2) * 2;
        float sA = 0.f, s2A = 0.f, sB = 0.f, s2B = 0.f;
        for (int j = h; j < nb; j += 8) {
            float4 v = *(const float4*)(sp4 + (size_t)j * T_LEN * 2);
            sA += v.x + v.y;  s2A = fmaf(v.x, v.x, s2A); s2A = fmaf(v.y, v.y, s2A);
            sB += v.z + v.w;  s2B = fmaf(v.z, v.z, s2B); s2B = fmaf(v.w, v.w, s2B);
            __nv_bfloat162 h0 = __floats2bfloat162_rn(v.x, v.z);
            float2 h0f = __bfloat1622float2(h0);
            __nv_bfloat162 l0 = __floats2bfloat162_rn(v.x - h0f.x, v.z - h0f.y);
            __nv_bfloat162 h1 = __floats2bfloat162_rn(v.y, v.w);
            float2 h1f = __bfloat1622float2(h1);
            __nv_bfloat162 l1 = __floats2bfloat162_rn(v.y - h1f.x, v.w - h1f.y);
            int o0 = ((2 * j)     * 72 + t2) * 2;
            int o1 = ((2 * j + 1) * 72 + t2) * 2;
            *(__nv_bfloat162*)(smem + SB_A_HI + o0) = h0;
            *(__nv_bfloat162*)(smem + SB_A_LO + o0) = l0;
            *(__nv_bfloat162*)(smem + SB_A_HI + o1) = h1;
            *(__nv_bfloat162*)(smem + SB_A_LO + o1) = l1;
        }
        ((float*)(smem + SB_PS))[h * 64 + t2]      = sA;
        ((float*)(smem + SB_PS))[h * 64 + t2 + 1]  = sB;
        ((float*)(smem + SB_PS2))[h * 64 + t2]     = s2A;
        ((float*)(smem + SB_PS2))[h * 64 + t2 + 1] = s2B;
    }
    // zero A pad rows [f, kpad): 36 u32 per row per buffer
    for (int i = tid; i < (kpad - f) * 36; i += 256) {
        int r = f + i / 36, c4 = i % 36;
        *(unsigned*)(smem + SB_A_HI + r * 144 + c4 * 4) = 0u;
        *(unsigned*)(smem + SB_A_LO + r * 144 + c4 * 4) = 0u;
    }
    __syncthreads();

    // ---- finalize stats | stage S1/S2 ----
    if (tid < 64) {
        int t = tid;
        float s = 0.f, s2 = 0.f;
#pragma unroll
        for (int h = 0; h < 8; ++h) {
            s  += ((float*)(smem + SB_PS))[h * 64 + t];
            s2 += ((float*)(smem + SB_PS2))[h * 64 + t];
        }
        float inv_f = 1.0f / (float)f;
        float m = s * inv_f;
        float var = fmaxf(s2 * inv_f - m * m, 0.f);
        ((float*)(smem + SB_MU))[t] = m;
        ((float*)(smem + SB_RS))[t] = rsqrtf(var + EPS);
    } else if (tid < 192) {
        int e = tid - 64;
        ((float*)(smem + SB_S1))[e] = g_S1[kb * EMBED + e];
        ((float*)(smem + SB_S2))[e] = g_S2[kb * EMBED + e];
    }

    // ---- MMA mainloop: warp tile 32t x 32e (warp grid 2t x 4e) ----
    const int wm = wid & 1, wn = wid >> 1;
    const int tb = wm * 32, n0 = wn * 32;
    const int lrow  = (lid & 7) + ((lid >> 4) << 3);
    const int lcol8 = ((lid >> 3) & 1) << 3;

    float acc[2][4][4];
#pragma unroll
    for (int m = 0; m < 2; ++m)
#pragma unroll
        for (int g = 0; g < 4; ++g)
#pragma unroll
            for (int q = 0; q < 4; ++q) acc[m][g][q] = 0.f;

    for (int c = 0; c < nch; ++c) {
        CP_WAIT0();
        __syncthreads();
        if (c + 1 < nch) {
            int buf = (c + 1) & 1;
            for (int m = tid; m < 512; m += 256) {
                int typ = m & 1, half = (m >> 1) & 1, e = m >> 2;
                const unsigned* src = (typ ? srcL : srcH) + e * (KPMAX / 2) + (c + 1) * 8 + half * 4;
                cp16(sb + SB_B + buf * 12288 + typ * 6144 + (e * 24 + half * 8) * 2, src);
            }
        }
        CP_COMMIT();

        const int k0 = c << 4;
        uint32_t ah[2][4], al[2][4];
#pragma unroll
        for (int m = 0; m < 2; ++m) {
            uint32_t ad = sb + SB_A_HI + ((k0 + lrow) * 72 + tb + m * 16 + lcol8) * 2;
            ldsm_x4_t(ah[m], ad);
            ldsm_x4_t(al[m], ad + (SB_A_LO - SB_A_HI));
        }
        const uint32_t bbase = sb + SB_B + (c & 1) * 12288;
#pragma unroll
        for (int gg = 0; gg < 2; ++gg) {
            uint32_t bd = bbase + ((n0 + gg * 16 + lrow) * 24 + lcol8) * 2;
            uint32_t bh[4], bl[4];
            ldsm_x4(bh, bd);
            ldsm_x4(bl, bd + 6144);
#pragma unroll
            for (int m = 0; m < 2; ++m) {
                mma_bf16(acc[m][2 * gg],     ah[m], bh);
                mma_bf16(acc[m][2 * gg + 1], ah[m], bh + 2);
                mma_bf16(acc[m][2 * gg],     al[m], bh);
                mma_bf16(acc[m][2 * gg + 1], al[m], bh + 2);
                mma_bf16(acc[m][2 * gg],     ah[m], bl);
                mma_bf16(acc[m][2 * gg + 1], ah[m], bl + 2);
            }
        }
    }

    // ---- epilogue: y = rs*(acc - mu*S1) + S2, DIRECT scattered STG ----
    // Per STG.32, the warp's 32 lanes cover 4 e-rows x 8 consecutive t
    // = 4 full 32B sectors -> 100% sector efficiency, no smem round-trip.
    {
        const float* mus = (const float*)(smem + SB_MU);
        const float* rss = (const float*)(smem + SB_RS);
        const float* s1s = (const float*)(smem + SB_S1);
        const float* s2s = (const float*)(smem + SB_S2);
        const size_t estr = (size_t)K_BANDS * T_LEN;
        float* ob = out + (((size_t)b * EMBED) * K_BANDS + kb) * T_LEN + t0;

#pragma unroll
        for (int m = 0; m < 2; ++m) {
            int t1 = tb + m * 16 + (lid >> 2);
            float mu0 = mus[t1],     rs0 = rss[t1];
            float mu1 = mus[t1 + 8], rs1 = rss[t1 + 8];
#pragma unroll
            for (int g = 0; g < 4; ++g) {
                int e0 = n0 + g * 8 + ((lid & 3) << 1);
                float s1a = s1s[e0],     s2a = s2s[e0];
                float s1b = s1s[e0 + 1], s2b = s2s[e0 + 1];
                float* a4 = acc[m][g];
                float* p0 = ob + (size_t)e0 * estr + t1;
                float* p1 = p0 + estr;
                p0[0] = fmaf(rs0, fmaf(-mu0, s1a, a4[0]), s2a);
                p1[0] = fmaf(rs0, fmaf(-mu0, s1b, a4[1]), s2b);
                p0[8] = fmaf(rs1, fmaf(-mu1, s1a, a4[2]), s2a);
                p1[8] = fmaf(rs1, fmaf(-mu1, s1b, a4[3]), s2b);
            }
        }
    }
}

extern "C" void kernel_launch(void* const* d_in, const int* in_sizes, int n_in,
                              void* d_out, int out_size) {
    const float* spec  = (const float*)d_in[0];
    const float* gamma = (const float*)d_in[1];
    const float* beta  = (const float*)d_in[2];
    const float* W     = (const float*)d_in[3];
    const float* bias  = (const float*)d_in[4];
    float* out = (float*)d_out;

    prep_kernel<<<dim3(K_BANDS, 8), 128>>>(W, gamma, beta, bias);

    cudaFuncSetAttribute(band_main, cudaFuncAttributeMaxDynamicSharedMemorySize, SM_TOT);
    dim3 grid(T_LEN / TT, B_SZ, K_BANDS);
    band_main<<<grid, 256, SM_TOT>>>(spec, out);
}

// round 15
// speedup vs baseline: 1.1822x; 1.0108x over previous
#include <cuda_runtime.h>
#include <cuda_bf16.h>
#include <cstdint>

#define K_BANDS 36
#define EMBED   128
#define MAXF    130
#define KPMAX   144
#define NB_TOT  1025
#define T_LEN   2048
#define B_SZ    8
#define TT      64
#define EPS     1e-5f

// ---- device scratch ----
__device__ float g_S1[K_BANDS * EMBED];
__device__ float g_S2[K_BANDS * EMBED];
// Wg hi/lo bf16x2 pairs, [k][e][KPMAX/2] (k-contig per e), zero-padded
__device__ __align__(16) unsigned g_Bh[K_BANDS * EMBED * (KPMAX / 2)];
__device__ __align__(16) unsigned g_Bl[K_BANDS * EMBED * (KPMAX / 2)];

__device__ __forceinline__ void band_params(int k, int& nb, int& start) {
    if (k < 20)      { nb = 16; start = 16 * k; }
    else if (k < 30) { nb = 32; start = 320 + 32 * (k - 20); }
    else if (k < 35) { nb = 64; start = 640 + 64 * (k - 30); }
    else             { nb = 65; start = 960; }
}

// grid (36, 8), 128 threads.
__global__ void prep_kernel(const float* __restrict__ W,
                            const float* __restrict__ gamma,
                            const float* __restrict__ beta,
                            const float* __restrict__ bias) {
    const int k = blockIdx.x, q = blockIdx.y;
    const int tid = threadIdx.x;
    int nb, start; band_params(k, nb, start);
    const int f = 2 * nb;
    const float* gk = gamma + (size_t)k * MAXF;
    const float* bk = beta  + (size_t)k * MAXF;

    {
        int el = tid >> 3, l = tid & 7;
        int e = q * 16 + el;
        const float* Wk = W + ((size_t)k * EMBED + e) * MAXF;
        float s1 = 0.f, s2 = 0.f;
        for (int ff = l; ff < f; ff += 8) {
            float w = Wk[ff];
            s1 += w * gk[ff];
            s2 += w * bk[ff];
        }
#pragma unroll
        for (int d = 1; d < 8; d <<= 1) {
            s1 += __shfl_xor_sync(0xFFFFFFFFu, s1, d);
            s2 += __shfl_xor_sync(0xFFFFFFFFu, s2, d);
        }
        if (l == 0) {
            g_S1[k * EMBED + e] = s1;
            g_S2[k * EMBED + e] = s2 + bias[k * EMBED + e];
        }
    }

    for (int idx = q * 1152 + tid; idx < (q + 1) * 1152; idx += 128) {
        int e = idx / (KPMAX / 2);
        int p = idx % (KPMAX / 2);
        int k0 = 2 * p, k1 = 2 * p + 1;
        const float* Wk = W + ((size_t)k * EMBED + e) * MAXF;
        float w0 = (k0 < f) ? Wk[k0] * gk[k0] : 0.f;
        float w1 = (k1 < f) ? Wk[k1] * gk[k1] : 0.f;
        __nv_bfloat162 h = __floats2bfloat162_rn(w0, w1);
        float2 hf = __bfloat1622float2(h);
        __nv_bfloat162 l = __floats2bfloat162_rn(w0 - hf.x, w1 - hf.y);
        size_t o = (size_t)k * EMBED * (KPMAX / 2) + idx;
        g_Bh[o] = *(unsigned*)&h;
        g_Bl[o] = *(unsigned*)&l;
    }
}

// ---- ptx helpers ----
__device__ __forceinline__ uint32_t smem_u32(const void* p) {
    uint32_t a;
    asm("{ .reg .u64 t; cvta.to.shared.u64 t, %1; cvt.u32.u64 %0, t; }" : "=r"(a) : "l"(p));
    return a;
}
__device__ __forceinline__ void cp16(uint32_t dst, const void* src) {
    asm volatile("cp.async.ca.shared.global [%0], [%1], 16;" :: "r"(dst), "l"(src));
}
#define CP_COMMIT() asm volatile("cp.async.commit_group;")
#define CP_WAIT0()  asm volatile("cp.async.wait_group 0;")

__device__ __forceinline__ void ldsm_x4(uint32_t* r, uint32_t addr) {
    asm volatile("ldmatrix.sync.aligned.m8n8.x4.shared.b16 {%0,%1,%2,%3}, [%4];"
        : "=r"(r[0]), "=r"(r[1]), "=r"(r[2]), "=r"(r[3]) : "r"(addr));
}
__device__ __forceinline__ void ldsm_x4_t(uint32_t* r, uint32_t addr) {
    asm volatile("ldmatrix.sync.aligned.m8n8.x4.trans.shared.b16 {%0,%1,%2,%3}, [%4];"
        : "=r"(r[0]), "=r"(r[1]), "=r"(r[2]), "=r"(r[3]) : "r"(addr));
}
__device__ __forceinline__ void mma_bf16(float* c, const uint32_t* a, const uint32_t* b) {
    asm volatile("mma.sync.aligned.m16n8k16.row.col.f32.bf16.bf16.f32 "
        "{%0,%1,%2,%3}, {%4,%5,%6,%7}, {%8,%9}, {%0,%1,%2,%3};"
        : "+f"(c[0]), "+f"(c[1]), "+f"(c[2]), "+f"(c[3])
        : "r"(a[0]), "r"(a[1]), "r"(a[2]), "r"(a[3]), "r"(b[0]), "r"(b[1]));
}

// ---- smem byte offsets ----
// A: [k<=144][t stride 72] bf16 hi/lo
#define SB_A_HI 0
#define SB_A_LO 20736
#define SB_B    41472          // 2 bufs x (hi 6144 + lo 6144); [e][k stride 24]
#define SB_PS   66048          // 8 x 64 floats
#define SB_PS2  68096
#define SB_MU   70144
#define SB_RS   70400
#define SB_S1   70656
#define SB_S2   71168
#define SM_TOT  71680

__global__ __launch_bounds__(256, 3)
void band_main(const float* __restrict__ spec, float* __restrict__ out) {
    const int kb = 35 - blockIdx.z;          // heavy bands first
    const int b  = blockIdx.y;
    const int t0 = blockIdx.x * TT;
    int nb, start; band_params(kb, nb, start);
    const int f    = 2 * nb;
    const int kpad = (f + 15) & ~15;
    const int nch  = kpad >> 4;

    extern __shared__ __align__(16) char smem[];
    const uint32_t sb = smem_u32(smem);
    const int tid = threadIdx.x;
    const int wid = tid >> 5;
    const int lid = tid & 31;

    const unsigned* srcH = g_Bh + (size_t)kb * EMBED * (KPMAX / 2);
    const unsigned* srcL = g_Bl + (size_t)kb * EMBED * (KPMAX / 2);

    // ---- issue B chunk 0 ----
    {
        for (int m = tid; m < 512; m += 256) {
            int typ = m & 1, half = (m >> 1) & 1, e = m >> 2;
            const unsigned* src = (typ ? srcL : srcH) + e * (KPMAX / 2) + half * 4;
            cp16(sb + SB_B + typ * 6144 + (e * 24 + half * 8) * 2, src);
        }
        CP_COMMIT();
    }

    // ---- fused stage A + stats: thread owns t-pair, 8-way k split ----
    {
        const int h  = tid >> 5;             // k-group 0..7
        const int t2 = lid * 2;              // t pair base 0..62
        const float* sp4 = spec + (((size_t)b * NB_TOT + start) * T_LEN + t0 + t2) * 2;
        float sA = 0.f, s2A = 0.f, sB = 0.f, s2B = 0.f;
        for (int j = h; j < nb; j += 8) {
            float4 v = *(const float4*)(sp4 + (size_t)j * T_LEN * 2);
            sA += v.x + v.y;  s2A = fmaf(v.x, v.x, s2A); s2A = fmaf(v.y, v.y, s2A);
            sB += v.z + v.w;  s2B = fmaf(v.z, v.z, s2B); s2B = fmaf(v.w, v.w, s2B);
            __nv_bfloat162 h0 = __floats2bfloat162_rn(v.x, v.z);
            float2 h0f = __bfloat1622float2(h0);
            __nv_bfloat162 l0 = __floats2bfloat162_rn(v.x - h0f.x, v.z - h0f.y);
            __nv_bfloat162 h1 = __floats2bfloat162_rn(v.y, v.w);
            float2 h1f = __bfloat1622float2(h1);
            __nv_bfloat162 l1 = __floats2bfloat162_rn(v.y - h1f.x, v.w - h1f.y);
            int o0 = ((2 * j)     * 72 + t2) * 2;
            int o1 = ((2 * j + 1) * 72 + t2) * 2;
            *(__nv_bfloat162*)(smem + SB_A_HI + o0) = h0;
            *(__nv_bfloat162*)(smem + SB_A_LO + o0) = l0;
            *(__nv_bfloat162*)(smem + SB_A_HI + o1) = h1;
            *(__nv_bfloat162*)(smem + SB_A_LO + o1) = l1;
        }
        ((float*)(smem + SB_PS))[h * 64 + t2]      = sA;
        ((float*)(smem + SB_PS))[h * 64 + t2 + 1]  = sB;
        ((float*)(smem + SB_PS2))[h * 64 + t2]     = s2A;
        ((float*)(smem + SB_PS2))[h * 64 + t2 + 1] = s2B;
    }
    // zero A pad rows [f, kpad): 36 u32 per row per buffer
    for (int i = tid; i < (kpad - f) * 36; i += 256) {
        int r = f + i / 36, c4 = i % 36;
        *(unsigned*)(smem + SB_A_HI + r * 144 + c4 * 4) = 0u;
        *(unsigned*)(smem + SB_A_LO + r * 144 + c4 * 4) = 0u;
    }
    __syncthreads();

    // ---- finalize stats | stage S1/S2 ----
    if (tid < 64) {
        int t = tid;
        float s = 0.f, s2 = 0.f;
#pragma unroll
        for (int h = 0; h < 8; ++h) {
            s  += ((float*)(smem + SB_PS))[h * 64 + t];
            s2 += ((float*)(smem + SB_PS2))[h * 64 + t];
        }
        float inv_f = 1.0f / (float)f;
        float m = s * inv_f;
        float var = fmaxf(s2 * inv_f - m * m, 0.f);
        ((float*)(smem + SB_MU))[t] = m;
        ((float*)(smem + SB_RS))[t] = rsqrtf(var + EPS);
    } else if (tid < 192) {
        int e = tid - 64;
        ((float*)(smem + SB_S1))[e] = g_S1[kb * EMBED + e];
        ((float*)(smem + SB_S2))[e] = g_S2[kb * EMBED + e];
    }

    // ---- MMA mainloop: warp tile 32t x 32e (warp grid 2t x 4e) ----
    const int wm = wid & 1, wn = wid >> 1;
    const int tb = wm * 32, n0 = wn * 32;
    const int lrow  = (lid & 7) + ((lid >> 4) << 3);
    const int lcol8 = ((lid >> 3) & 1) << 3;

    float acc[2][4][4];
#pragma unroll
    for (int m = 0; m < 2; ++m)
#pragma unroll
        for (int g = 0; g < 4; ++g)
#pragma unroll
            for (int q = 0; q < 4; ++q) acc[m][g][q] = 0.f;

    // hoisted ldsm base addresses (chunk-invariant parts)
    const uint32_t adA  = sb + SB_A_HI + (lrow * 72 + tb + lcol8) * 2;  // + m*32 + c*2304
    const uint32_t bd0  = sb + SB_B + ((n0 + lrow) * 24 + lcol8) * 2;   // + gg*768 + buf*12288

    for (int c = 0; c < nch; ++c) {
        CP_WAIT0();
        __syncthreads();
        if (c + 1 < nch) {
            int buf = (c + 1) & 1;
            for (int m = tid; m < 512; m += 256) {
                int typ = m & 1, half = (m >> 1) & 1, e = m >> 2;
                const unsigned* src = (typ ? srcL : srcH) + e * (KPMAX / 2) + (c + 1) * 8 + half * 4;
                cp16(sb + SB_B + buf * 12288 + typ * 6144 + (e * 24 + half * 8) * 2, src);
            }
        }
        CP_COMMIT();

        // ---- load ALL fragments first ----
        uint32_t ah[2][4], al[2][4], bhf[2][4], blf[2][4];
        const uint32_t aA = adA + c * 2304;           // c*16 rows * 72 * 2B
#pragma unroll
        for (int m = 0; m < 2; ++m) {
            ldsm_x4_t(ah[m], aA + m * 32);
            ldsm_x4_t(al[m], aA + m * 32 + (SB_A_LO - SB_A_HI));
        }
        const uint32_t bB = bd0 + (c & 1) * 12288;
#pragma unroll
        for (int gg = 0; gg < 2; ++gg) {
            ldsm_x4(bhf[gg], bB + gg * 768);          // 16 e-rows * 24 * 2B
            ldsm_x4(blf[gg], bB + gg * 768 + 6144);
        }

        // ---- 3 passes, 8 distinct accumulators per pass (reuse dist 8) ----
#pragma unroll
        for (int m = 0; m < 2; ++m)
#pragma unroll
            for (int gg = 0; gg < 2; ++gg) {
                mma_bf16(acc[m][2 * gg],     ah[m], bhf[gg]);
                mma_bf16(acc[m][2 * gg + 1], ah[m], bhf[gg] + 2);
            }
#pragma unroll
        for (int m = 0; m < 2; ++m)
#pragma unroll
            for (int gg = 0; gg < 2; ++gg) {
                mma_bf16(acc[m][2 * gg],     al[m], bhf[gg]);
                mma_bf16(acc[m][2 * gg + 1], al[m], bhf[gg] + 2);
            }
#pragma unroll
        for (int m = 0; m < 2; ++m)
#pragma unroll
            for (int gg = 0; gg < 2; ++gg) {
                mma_bf16(acc[m][2 * gg],     ah[m], blf[gg]);
                mma_bf16(acc[m][2 * gg + 1], ah[m], blf[gg] + 2);
            }
    }

    // ---- epilogue: y = rs*(acc - mu*S1) + S2, direct scattered STG ----
    {
        const float* mus = (const float*)(smem + SB_MU);
        const float* rss = (const float*)(smem + SB_RS);
        const float* s1s = (const float*)(smem + SB_S1);
        const float* s2s = (const float*)(smem + SB_S2);
        const size_t estr = (size_t)K_BANDS * T_LEN;
        float* ob = out + (((size_t)b * EMBED) * K_BANDS + kb) * T_LEN + t0;

#pragma unroll
        for (int m = 0; m < 2; ++m) {
            int t1 = tb + m * 16 + (lid >> 2);
            float mu0 = mus[t1],     rs0 = rss[t1];
            float mu1 = mus[t1 + 8], rs1 = rss[t1 + 8];
#pragma unroll
            for (int g = 0; g < 4; ++g) {
                int e0 = n0 + g * 8 + ((lid & 3) << 1);
                float2 s1 = *(const float2*)&s1s[e0];
                float2 s2 = *(const float2*)&s2s[e0];
                float* a4 = acc[m][g];
                float* p0 = ob + (size_t)e0 * estr + t1;
                float* p1 = p0 + estr;
                p0[0] = fmaf(rs0, fmaf(-mu0, s1.x, a4[0]), s2.x);
                p1[0] = fmaf(rs0, fmaf(-mu0, s1.y, a4[1]), s2.y);
                p0[8] = fmaf(rs1, fmaf(-mu1, s1.x, a4[2]), s2.x);
                p1[8] = fmaf(rs1, fmaf(-mu1, s1.y, a4[3]), s2.y);
            }
        }
    }
}

extern "C" void kernel_launch(void* const* d_in, const int* in_sizes, int n_in,
                              void* d_out, int out_size) {
    const float* spec  = (const float*)d_in[0];
    const float* gamma = (const float*)d_in[1];
    const float* beta  = (const float*)d_in[2];
    const float* W     = (const float*)d_in[3];
    const float* bias  = (const float*)d_in[4];
    float* out = (float*)d_out;

    prep_kernel<<<dim3(K_BANDS, 8), 128>>>(W, gamma, beta, bias);

    cudaFuncSetAttribute(band_main, cudaFuncAttributeMaxDynamicSharedMemorySize, SM_TOT);
    dim3 grid(T_LEN / TT, B_SZ, K_BANDS);
    band_main<<<grid, 256, SM_TOT>>>(spec, out);
}

// round 16
// speedup vs baseline: 1.3728x; 1.1613x over previous
#include <cuda_runtime.h>
#include <cuda_bf16.h>
#include <cstdint>

#define K_BANDS 36
#define EMBED   128
#define MAXF    130
#define KPMAX   144
#define NB_TOT  1025
#define T_LEN   2048
#define B_SZ    8
#define TT      64
#define EPS     1e-5f

// ---- device scratch ----
__device__ float g_S1[K_BANDS * EMBED];
__device__ float g_S2[K_BANDS * EMBED];
// Wg hi/lo bf16x2 pairs, [k][e][KPMAX/2] (k-contig per e), zero-padded
__device__ __align__(16) unsigned g_Bh[K_BANDS * EMBED * (KPMAX / 2)];
__device__ __align__(16) unsigned g_Bl[K_BANDS * EMBED * (KPMAX / 2)];

__device__ __forceinline__ void band_params(int k, int& nb, int& start) {
    if (k < 20)      { nb = 16; start = 16 * k; }
    else if (k < 30) { nb = 32; start = 320 + 32 * (k - 20); }
    else if (k < 35) { nb = 64; start = 640 + 64 * (k - 30); }
    else             { nb = 65; start = 960; }
}

// grid (36, 8), 128 threads.
__global__ void prep_kernel(const float* __restrict__ W,
                            const float* __restrict__ gamma,
                            const float* __restrict__ beta,
                            const float* __restrict__ bias) {
    const int k = blockIdx.x, q = blockIdx.y;
    const int tid = threadIdx.x;
    int nb, start; band_params(k, nb, start);
    const int f = 2 * nb;
    const float* gk = gamma + (size_t)k * MAXF;
    const float* bk = beta  + (size_t)k * MAXF;

    {
        int el = tid >> 3, l = tid & 7;
        int e = q * 16 + el;
        const float* Wk = W + ((size_t)k * EMBED + e) * MAXF;
        float s1 = 0.f, s2 = 0.f;
        for (int ff = l; ff < f; ff += 8) {
            float w = Wk[ff];
            s1 += w * gk[ff];
            s2 += w * bk[ff];
        }
#pragma unroll
        for (int d = 1; d < 8; d <<= 1) {
            s1 += __shfl_xor_sync(0xFFFFFFFFu, s1, d);
            s2 += __shfl_xor_sync(0xFFFFFFFFu, s2, d);
        }
        if (l == 0) {
            g_S1[k * EMBED + e] = s1;
            g_S2[k * EMBED + e] = s2 + bias[k * EMBED + e];
        }
    }

    for (int idx = q * 1152 + tid; idx < (q + 1) * 1152; idx += 128) {
        int e = idx / (KPMAX / 2);
        int p = idx % (KPMAX / 2);
        int k0 = 2 * p, k1 = 2 * p + 1;
        const float* Wk = W + ((size_t)k * EMBED + e) * MAXF;
        float w0 = (k0 < f) ? Wk[k0] * gk[k0] : 0.f;
        float w1 = (k1 < f) ? Wk[k1] * gk[k1] : 0.f;
        __nv_bfloat162 h = __floats2bfloat162_rn(w0, w1);
        float2 hf = __bfloat1622float2(h);
        __nv_bfloat162 l = __floats2bfloat162_rn(w0 - hf.x, w1 - hf.y);
        size_t o = (size_t)k * EMBED * (KPMAX / 2) + idx;
        g_Bh[o] = *(unsigned*)&h;
        g_Bl[o] = *(unsigned*)&l;
    }
}

// ---- ptx helpers ----
__device__ __forceinline__ uint32_t smem_u32(const void* p) {
    uint32_t a;
    asm("{ .reg .u64 t; cvta.to.shared.u64 t, %1; cvt.u32.u64 %0, t; }" : "=r"(a) : "l"(p));
    return a;
}
__device__ __forceinline__ void cp16(uint32_t dst, const void* src) {
    asm volatile("cp.async.cg.shared.global [%0], [%1], 16;" :: "r"(dst), "l"(src));
}
#define CP_COMMIT() asm volatile("cp.async.commit_group;")
#define CP_WAIT0()  asm volatile("cp.async.wait_group 0;")

__device__ __forceinline__ void ldsm_x4(uint32_t* r, uint32_t addr) {
    asm volatile("ldmatrix.sync.aligned.m8n8.x4.shared.b16 {%0,%1,%2,%3}, [%4];"
        : "=r"(r[0]), "=r"(r[1]), "=r"(r[2]), "=r"(r[3]) : "r"(addr));
}
__device__ __forceinline__ void ldsm_x4_t(uint32_t* r, uint32_t addr) {
    asm volatile("ldmatrix.sync.aligned.m8n8.x4.trans.shared.b16 {%0,%1,%2,%3}, [%4];"
        : "=r"(r[0]), "=r"(r[1]), "=r"(r[2]), "=r"(r[3]) : "r"(addr));
}
__device__ __forceinline__ void mma_bf16(float* c, const uint32_t* a, const uint32_t* b) {
    asm volatile("mma.sync.aligned.m16n8k16.row.col.f32.bf16.bf16.f32 "
        "{%0,%1,%2,%3}, {%4,%5,%6,%7}, {%8,%9}, {%0,%1,%2,%3};"
        : "+f"(c[0]), "+f"(c[1]), "+f"(c[2]), "+f"(c[3])
        : "r"(a[0]), "r"(a[1]), "r"(a[2]), "r"(a[3]), "r"(b[0]), "r"(b[1]));
}

// ---- smem byte offsets ----
// A: [k<=144][t stride 72] bf16 hi/lo
#define SB_A_HI 0
#define SB_A_LO 20736
#define SB_B    41472          // 2 bufs x (hi 6144 + lo 6144); [e][k stride 24]
#define SB_PS   66048          // 8 x 64 floats
#define SB_PS2  68096
#define SB_MU   70144
#define SB_RS   70400
#define SB_S1   70656
#define SB_S2   71168
#define SM_TOT  71680

__global__ __launch_bounds__(256, 3)
void band_main(const float* __restrict__ spec, float* __restrict__ out) {
    const int kb = 35 - blockIdx.z;          // heavy bands first
    const int b  = blockIdx.y;
    const int t0 = blockIdx.x * TT;
    int nb, start; band_params(kb, nb, start);
    const int f    = 2 * nb;
    const int kpad = (f + 15) & ~15;
    const int nch  = kpad >> 4;

    extern __shared__ __align__(16) char smem[];
    const uint32_t sb = smem_u32(smem);
    const int tid = threadIdx.x;
    const int wid = tid >> 5;
    const int lid = tid & 31;

    const unsigned* srcH = g_Bh + (size_t)kb * EMBED * (KPMAX / 2);
    const unsigned* srcL = g_Bl + (size_t)kb * EMBED * (KPMAX / 2);

    // ---- issue B chunk 0 (and chunk 1 too when nch==2: both fit the 2 bufs) ----
    {
        for (int m = tid; m < 512; m += 256) {
            int typ = m & 1, half = (m >> 1) & 1, e = m >> 2;
            const unsigned* src = (typ ? srcL : srcH) + e * (KPMAX / 2) + half * 4;
            cp16(sb + SB_B + typ * 6144 + (e * 24 + half * 8) * 2, src);
        }
        if (nch == 2) {
            for (int m = tid; m < 512; m += 256) {
                int typ = m & 1, half = (m >> 1) & 1, e = m >> 2;
                const unsigned* src = (typ ? srcL : srcH) + e * (KPMAX / 2) + 8 + half * 4;
                cp16(sb + SB_B + 12288 + typ * 6144 + (e * 24 + half * 8) * 2, src);
            }
        }
        CP_COMMIT();
    }

    // ---- fused stage A + stats: thread owns t-pair, 8-way k split ----
    {
        const int h  = tid >> 5;             // k-group 0..7
        const int t2 = lid * 2;              // t pair base 0..62
        const float* sp4 = spec + (((size_t)b * NB_TOT + start) * T_LEN + t0 + t2) * 2;
        float sA = 0.f, s2A = 0.f, sB = 0.f, s2B = 0.f;
        for (int j = h; j < nb; j += 8) {
            float4 v = *(const float4*)(sp4 + (size_t)j * T_LEN * 2);
            sA += v.x + v.y;  s2A = fmaf(v.x, v.x, s2A); s2A = fmaf(v.y, v.y, s2A);
            sB += v.z + v.w;  s2B = fmaf(v.z, v.z, s2B); s2B = fmaf(v.w, v.w, s2B);
            __nv_bfloat162 h0 = __floats2bfloat162_rn(v.x, v.z);
            float2 h0f = __bfloat1622float2(h0);
            __nv_bfloat162 l0 = __floats2bfloat162_rn(v.x - h0f.x, v.z - h0f.y);
            __nv_bfloat162 h1 = __floats2bfloat162_rn(v.y, v.w);
            float2 h1f = __bfloat1622float2(h1);
            __nv_bfloat162 l1 = __floats2bfloat162_rn(v.y - h1f.x, v.w - h1f.y);
            int o0 = ((2 * j)     * 72 + t2) * 2;
            int o1 = ((2 * j + 1) * 72 + t2) * 2;
            *(__nv_bfloat162*)(smem + SB_A_HI + o0) = h0;
            *(__nv_bfloat162*)(smem + SB_A_LO + o0) = l0;
            *(__nv_bfloat162*)(smem + SB_A_HI + o1) = h1;
            *(__nv_bfloat162*)(smem + SB_A_LO + o1) = l1;
        }
        ((float*)(smem + SB_PS))[h * 64 + t2]      = sA;
        ((float*)(smem + SB_PS))[h * 64 + t2 + 1]  = sB;
        ((float*)(smem + SB_PS2))[h * 64 + t2]     = s2A;
        ((float*)(smem + SB_PS2))[h * 64 + t2 + 1] = s2B;
    }
    // zero A pad rows [f, kpad): 36 u32 per row per buffer
    for (int i = tid; i < (kpad - f) * 36; i += 256) {
        int r = f + i / 36, c4 = i % 36;
        *(unsigned*)(smem + SB_A_HI + r * 144 + c4 * 4) = 0u;
        *(unsigned*)(smem + SB_A_LO + r * 144 + c4 * 4) = 0u;
    }
    __syncthreads();

    // ---- finalize stats | stage S1/S2 ----
    if (tid < 64) {
        int t = tid;
        float s = 0.f, s2 = 0.f;
#pragma unroll
        for (int h = 0; h < 8; ++h) {
            s  += ((float*)(smem + SB_PS))[h * 64 + t];
            s2 += ((float*)(smem + SB_PS2))[h * 64 + t];
        }
        float inv_f = 1.0f / (float)f;
        float m = s * inv_f;
        float var = fmaxf(s2 * inv_f - m * m, 0.f);
        ((float*)(smem + SB_MU))[t] = m;
        ((float*)(smem + SB_RS))[t] = rsqrtf(var + EPS);
    } else if (tid < 192) {
        int e = tid - 64;
        ((float*)(smem + SB_S1))[e] = g_S1[kb * EMBED + e];
        ((float*)(smem + SB_S2))[e] = g_S2[kb * EMBED + e];
    }

    // ---- MMA mainloop: warp tile 32t x 32e (warp grid 2t x 4e) ----
    const int wm = wid & 1, wn = wid >> 1;
    const int tb = wm * 32, n0 = wn * 32;
    const int lrow  = (lid & 7) + ((lid >> 4) << 3);
    const int lcol8 = ((lid >> 3) & 1) << 3;

    float acc[2][4][4];
#pragma unroll
    for (int m = 0; m < 2; ++m)
#pragma unroll
        for (int g = 0; g < 4; ++g)
#pragma unroll
            for (int q = 0; q < 4; ++q) acc[m][g][q] = 0.f;

    // hoisted ldsm base addresses (chunk-invariant parts)
    const uint32_t adA  = sb + SB_A_HI + (lrow * 72 + tb + lcol8) * 2;  // + m*32 + c*2304
    const uint32_t bd0  = sb + SB_B + ((n0 + lrow) * 24 + lcol8) * 2;   // + gg*768 + buf*12288

    // one chunk of fragment loads + 24 MMAs (3 passes, reuse distance 8)
    auto chunk_body = [&](int c, uint32_t bB) {
        uint32_t ah[2][4], al[2][4], bhf[2][4], blf[2][4];
        const uint32_t aA = adA + c * 2304;           // c*16 rows * 72 * 2B
#pragma unroll
        for (int m = 0; m < 2; ++m) {
            ldsm_x4_t(ah[m], aA + m * 32);
            ldsm_x4_t(al[m], aA + m * 32 + (SB_A_LO - SB_A_HI));
        }
#pragma unroll
        for (int gg = 0; gg < 2; ++gg) {
            ldsm_x4(bhf[gg], bB + gg * 768);          // 16 e-rows * 24 * 2B
            ldsm_x4(blf[gg], bB + gg * 768 + 6144);
        }
#pragma unroll
        for (int m = 0; m < 2; ++m)
#pragma unroll
            for (int gg = 0; gg < 2; ++gg) {
                mma_bf16(acc[m][2 * gg],     ah[m], bhf[gg]);
                mma_bf16(acc[m][2 * gg + 1], ah[m], bhf[gg] + 2);
            }
#pragma unroll
        for (int m = 0; m < 2; ++m)
#pragma unroll
            for (int gg = 0; gg < 2; ++gg) {
                mma_bf16(acc[m][2 * gg],     al[m], bhf[gg]);
                mma_bf16(acc[m][2 * gg + 1], al[m], bhf[gg] + 2);
            }
#pragma unroll
        for (int m = 0; m < 2; ++m)
#pragma unroll
            for (int gg = 0; gg < 2; ++gg) {
                mma_bf16(acc[m][2 * gg],     ah[m], blf[gg]);
                mma_bf16(acc[m][2 * gg + 1], ah[m], blf[gg] + 2);
            }
    };

    if (nch == 2) {
        // fast path (55% of CTAs): all B already inflight, ONE wait + ONE sync
        CP_WAIT0();
        __syncthreads();
        chunk_body(0, bd0);
        chunk_body(1, bd0 + 12288);
    } else {
        for (int c = 0; c < nch; ++c) {
            CP_WAIT0();
            __syncthreads();
            if (c + 1 < nch) {
                int buf = (c + 1) & 1;
                for (int m = tid; m < 512; m += 256) {
                    int typ = m & 1, half = (m >> 1) & 1, e = m >> 2;
                    const unsigned* src = (typ ? srcL : srcH) + e * (KPMAX / 2) + (c + 1) * 8 + half * 4;
                    cp16(sb + SB_B + buf * 12288 + typ * 6144 + (e * 24 + half * 8) * 2, src);
                }
            }
            CP_COMMIT();
            chunk_body(c, bd0 + (c & 1) * 12288);
        }
    }

    // ---- epilogue: y = rs*(acc - mu*S1) + S2, direct scattered STG ----
    {
        const float* mus = (const float*)(smem + SB_MU);
        const float* rss = (const float*)(smem + SB_RS);
        const float* s1s = (const float*)(smem + SB_S1);
        const float* s2s = (const float*)(smem + SB_S2);
        const size_t estr = (size_t)K_BANDS * T_LEN;
        float* ob = out + (((size_t)b * EMBED) * K_BANDS + kb) * T_LEN + t0;

#pragma unroll
        for (int m = 0; m < 2; ++m) {
            int t1 = tb + m * 16 + (lid >> 2);
            float mu0 = mus[t1],     rs0 = rss[t1];
            float mu1 = mus[t1 + 8], rs1 = rss[t1 + 8];
#pragma unroll
            for (int g = 0; g < 4; ++g) {
                int e0 = n0 + g * 8 + ((lid & 3) << 1);
                float2 s1 = *(const float2*)&s1s[e0];
                float2 s2 = *(const float2*)&s2s[e0];
                float* a4 = acc[m][g];
                float* p0 = ob + (size_t)e0 * estr + t1;
                float* p1 = p0 + estr;
                p0[0] = fmaf(rs0, fmaf(-mu0, s1.x, a4[0]), s2.x);
                p1[0] = fmaf(rs0, fmaf(-mu0, s1.y, a4[1]), s2.y);
                p0[8] = fmaf(rs1, fmaf(-mu1, s1.x, a4[2]), s2.x);
                p1[8] = fmaf(rs1, fmaf(-mu1, s1.y, a4[3]), s2.y);
            }
        }
    }
}

extern "C" void kernel_launch(void* const* d_in, const int* in_sizes, int n_in,
                              void* d_out, int out_size) {
    const float* spec  = (const float*)d_in[0];
    const float* gamma = (const float*)d_in[1];
    const float* beta  = (const float*)d_in[2];
    const float* W     = (const float*)d_in[3];
    const float* bias  = (const float*)d_in[4];
    float* out = (float*)d_out;

    prep_kernel<<<dim3(K_BANDS, 8), 128>>>(W, gamma, beta, bias);

    cudaFuncSetAttribute(band_main, cudaFuncAttributeMaxDynamicSharedMemorySize, SM_TOT);
    dim3 grid(T_LEN / TT, B_SZ, K_BANDS);
    band_main<<<grid, 256, SM_TOT>>>(spec, out);
}